// round 11
// baseline (speedup 1.0000x reference)
#include <cuda_runtime.h>

#define NB 8
#define NX 256
#define NC 256
#define KSEG 4
#define KLEN 64   /* NX / KSEG */
#define KC 8      /* smem chunk depth */

typedef unsigned long long u64;

// Split-K partial Gram matrices: [seg][b][c*NC+d]  (8 MB)
__device__ float g_G[KSEG * NB * NC * NC];
// Diagonal partials, seg-interleaved: [b][c][seg]  (32 KB, float4-loadable)
__device__ float g_Sp2[NB * NC * KSEG];

__device__ __forceinline__ u64 ffma2(u64 a, u64 b, u64 c) {
    u64 d;
    asm("fma.rn.f32x2 %0, %1, %2, %3;" : "=l"(d) : "l"(a), "l"(b), "l"(c));
    return d;
}
__device__ __forceinline__ u64 pack2(float x) {
    u64 d;
    unsigned xi = __float_as_uint(x);
    asm("mov.b64 %0, {%1, %1};" : "=l"(d) : "r"(xi));
    return d;
}

// ---------------------------------------------------------------------------
// K1: partial Gram  G[seg][b] += f[:,c]^T f[:,d] over k in [seg*64, seg*64+64)
//     f computed on the fly from amp/ph. 128x128 tile, 8x8 micro-tile,
//     packed f32x2 FMAs. grid = (16, 8): blockIdx.x = seg*4+quad, .y = b
//     Prologue: each block zeroes its 512-float slice of out (for k_mask
//     atomics) — no extra launch.
// ---------------------------------------------------------------------------
__global__ __launch_bounds__(256) void k_gram(const float* __restrict__ amp,
                                              const float* __restrict__ ph,
                                              const float* __restrict__ wap,
                                              const float* __restrict__ wpp,
                                              float* __restrict__ out) {
    __shared__ __align__(16) float As[KC][128];
    __shared__ __align__(16) float Bs[KC][128];

    int b = blockIdx.y;
    int q = blockIdx.x & 3;
    int seg = blockIdx.x >> 2;
    int tid = threadIdx.x;

    // zero output slice (128 blocks x 512 floats = 65536)
    {
        int bid = b * 16 + blockIdx.x;
        float2* oz = (float2*)(out + bid * 512);
        oz[tid] = make_float2(0.f, 0.f);
    }

    int cBase = (q >> 1) * 128;
    int dBase = (q & 1) * 128;
    int tx = tid & 15;       // 16 col groups x 8 cols
    int ty = tid >> 4;       // 16 row groups x 8 rows
    int sr = tid >> 5;       // staging row 0..7
    int sc = (tid & 31) * 4; // staging col 0..124

    float wa = wap[0], wp = wpp[0];
    const float* ab = amp + b * NX * NC;
    const float* pb = ph + b * NX * NC;

    u64 acc[8][4];
#pragma unroll
    for (int i = 0; i < 8; i++)
#pragma unroll
        for (int j = 0; j < 4; j++) acc[i][j] = 0ull;

    int k0 = seg * KLEN;

    float4 ra, rp, rb, rq;
    {
        int krow = k0 + sr;
        ra = *(const float4*)(ab + krow * NC + cBase + sc);
        rp = *(const float4*)(pb + krow * NC + cBase + sc);
        rb = *(const float4*)(ab + krow * NC + dBase + sc);
        rq = *(const float4*)(pb + krow * NC + dBase + sc);
    }

    for (int ch = 0; ch < KLEN / KC; ch++) {
        __syncthreads();
        float4 fa = make_float4(wa * ra.x + wp * rp.x, wa * ra.y + wp * rp.y,
                                wa * ra.z + wp * rp.z, wa * ra.w + wp * rp.w);
        float4 fb = make_float4(wa * rb.x + wp * rq.x, wa * rb.y + wp * rq.y,
                                wa * rb.z + wp * rq.z, wa * rb.w + wp * rq.w);
        *(float4*)&As[sr][sc] = fa;
        *(float4*)&Bs[sr][sc] = fb;
        __syncthreads();

        if (ch + 1 < KLEN / KC) {
            int krow = k0 + (ch + 1) * KC + sr;
            ra = *(const float4*)(ab + krow * NC + cBase + sc);
            rp = *(const float4*)(pb + krow * NC + cBase + sc);
            rb = *(const float4*)(ab + krow * NC + dBase + sc);
            rq = *(const float4*)(pb + krow * NC + dBase + sc);
        }

#pragma unroll
        for (int k = 0; k < KC; k++) {
            float4 a0 = *(const float4*)&As[k][ty * 8];
            float4 a1 = *(const float4*)&As[k][ty * 8 + 4];
            const u64* brow = (const u64*)&Bs[k][tx * 8];
            u64 b2[4];
            b2[0] = brow[0]; b2[1] = brow[1]; b2[2] = brow[2]; b2[3] = brow[3];
            float av[8] = {a0.x, a0.y, a0.z, a0.w, a1.x, a1.y, a1.z, a1.w};
#pragma unroll
            for (int i = 0; i < 8; i++) {
                u64 ai = pack2(av[i]);
#pragma unroll
                for (int j = 0; j < 4; j++) acc[i][j] = ffma2(ai, b2[j], acc[i][j]);
            }
        }
    }

    float* Gp = g_G + (size_t)(seg * NB + b) * NC * NC;
#pragma unroll
    for (int i = 0; i < 8; i++) {
        int c = cBase + ty * 8 + i;
        u64* dst = (u64*)(Gp + c * NC + dBase + tx * 8);
        dst[0] = acc[i][0]; dst[1] = acc[i][1]; dst[2] = acc[i][2]; dst[3] = acc[i][3];
    }

    // diagonal partials, seg-interleaved layout [b][c][seg]
    if (cBase == dBase && tx == ty) {
#pragma unroll
        for (int i = 0; i < 8; i++) {
            int c = cBase + ty * 8 + i;
            u64 v = acc[i][i >> 1];
            float f = (i & 1) ? __uint_as_float((unsigned)(v >> 32))
                              : __uint_as_float((unsigned)(v & 0xffffffffu));
            g_Sp2[(b * NC + c) * KSEG + seg] = f;
        }
    }
}

// ---------------------------------------------------------------------------
// K2: grid = 2048 (b*NC + c), block = 256 (d). Per thread:
//     Gv = sum of 4 seg partials; Sd from one float4; Sc via smem;
//     D = Ad^2*(Sc+Sd-2G)+1e-10; Dmin = block-min over d != c;
//     r = .99*Dmin/(D-.99*Dmin); sample r^2*(-ln u1) > -ln u0 with
//     __logf fast path + precise-logf fallback inside certainty margin;
//     predicated atomicAdd(out, 1/8) — exact in any order.
// ---------------------------------------------------------------------------
__global__ __launch_bounds__(256) void k_mask(const float* __restrict__ A,
                                              const float* __restrict__ gu,
                                              float* __restrict__ out) {
    int bc = blockIdx.x;
    int b = bc >> 8;
    int c = bc & 255;
    int d = threadIdx.x;
    __shared__ float sSc;
    __shared__ float red[8];

    // independent loads, all issued up front
    float g0 = g_G[(size_t)(0 * NB + b) * NC * NC + c * NC + d];
    float g1 = g_G[(size_t)(1 * NB + b) * NC * NC + c * NC + d];
    float g2 = g_G[(size_t)(2 * NB + b) * NC * NC + c * NC + d];
    float g3 = g_G[(size_t)(3 * NB + b) * NC * NC + c * NC + d];
    float4 s4 = *(const float4*)(g_Sp2 + (b * NC + d) * KSEG);
    float2 u = *(const float2*)(gu + ((size_t)bc * NC + d) * 2);
    float Ad = A[d * (NC + 1)];

    float Sd = (s4.x + s4.y) + (s4.z + s4.w);
    if (d == c) sSc = Sd;
    float Gv = (g0 + g1) + (g2 + g3);
    float Ad2 = Ad * Ad;
    __syncthreads();

    float D = Ad2 * (sSc + Sd - 2.f * Gv) + 1e-10f;
    float m = (d == c) ? __int_as_float(0x7f800000) : D;
#pragma unroll
    for (int o = 16; o > 0; o >>= 1)
        m = fminf(m, __shfl_xor_sync(0xffffffffu, m, o));
    if ((d & 31) == 0) red[d >> 5] = m;
    __syncthreads();
    float Dmin = fminf(fminf(fminf(red[0], red[1]), fminf(red[2], red[3])),
                       fminf(fminf(red[4], red[5]), fminf(red[6], red[7])));

    const float RDIAG = 0.99f / (1.0f - 0.99f);
    float r;
    if (d == c) {
        r = RDIAG;
    } else {
        float num = 0.99f * Dmin;
        r = num / (D - num);
    }
    float r2 = r * r;

    float t0 = -__logf(u.x);
    float t1 = -__logf(u.y);
    float diff = r2 * t1 - t0;
    float thr = 1e-6f * (r2 * fmaxf(t1, 1.f) + fmaxf(t0, 1.f));
    bool take;
    if (fabsf(diff) > thr) {
        take = diff > 0.f;
    } else {
        float t0p = -logf(u.x);
        float t1p = -logf(u.y);
        take = r2 * t1p > t0p;
    }
    if (take) atomicAdd(&out[c * NC + d], 0.125f);
}

// ---------------------------------------------------------------------------
extern "C" void kernel_launch(void* const* d_in, const int* in_sizes, int n_in,
                              void* d_out, int out_size) {
    const float* amp = (const float*)d_in[0];
    const float* ph  = (const float*)d_in[1];
    const float* A   = (const float*)d_in[2];
    const float* wa  = (const float*)d_in[3];
    const float* wp  = (const float*)d_in[4];
    const float* gu  = (const float*)d_in[5];
    float* out = (float*)d_out;

    k_gram<<<dim3(16, NB), 256>>>(amp, ph, wa, wp, out);
    k_mask<<<NB * NC, 256>>>(A, gu, out);
}